// round 4
// baseline (speedup 1.0000x reference)
#include <cuda_runtime.h>
#include <math.h>

// Problem constants
#define B_  8
#define L_  256
#define DM_ 1024
#define DI_ 2048
#define N_  16
#define K_  4
#define NL_ 4
#define DTR_ 128
#define P_  97
#define M_TOK (B_*L_)          // 2048 token rows
#define XPW_ (DTR_ + 2*N_)     // 160

// GEMM tiling
#define BM 128
#define BN 128
#define BK 16
#define SSTA 132               // smem row stride in uint2 elems ([k][m] layout)
#define STG (BK*SSTA)          // uint2 elems per stage per matrix
#define GEMM_SMEM (4*STG*sizeof(uint2))   // 2 stages x 2 matrices

// ---------------- scratch (static device globals; no allocation) ----------------
__device__ __align__(16) float g_h [M_TOK*DM_];
__device__ __align__(16) float g_x [M_TOK*DM_];
__device__ __align__(16) float g_xz[M_TOK*2*DI_];
__device__ __align__(16) float g_xb[M_TOK*DI_];
__device__ __align__(16) float g_xp[M_TOK*XPW_];
__device__ __align__(16) float g_dl[M_TOK*DI_];
__device__ __align__(16) float g_y [M_TOK*DI_];
__device__ __align__(16) float g_fin[B_*DM_];

// ---------------- embedding ----------------
__global__ void embed_k(const int* __restrict__ tok, const float* __restrict__ te,
                        const float* __restrict__ pe, float* __restrict__ h) {
    int row = blockIdx.x;
    int l = row & (L_ - 1);
    int t = tok[row];
    const float* tsrc = te + (long)t * DM_;
    const float* psrc = pe + (long)l * DM_;
    float* dst = h + (long)row * DM_;
    for (int d = threadIdx.x; d < DM_; d += 256)
        dst[d] = tsrc[d] + psrc[d];
}

// ---------------- layernorm ----------------
__global__ void ln_k(const float* __restrict__ in, long istride,
                     float* __restrict__ out, long ostride,
                     const float* __restrict__ w, const float* __restrict__ bb) {
    __shared__ float red[8];
    __shared__ float s_mean, s_rstd;
    int t = threadIdx.x;
    int row = blockIdx.x;
    const float* src = in + (long)row * istride;
    float v[4];
    float s = 0.f;
#pragma unroll
    for (int i = 0; i < 4; i++) { v[i] = src[t + i*256]; s += v[i]; }
#pragma unroll
    for (int o = 16; o; o >>= 1) s += __shfl_xor_sync(~0u, s, o);
    if ((t & 31) == 0) red[t >> 5] = s;
    __syncthreads();
    if (t < 32) {
        float x = (t < 8) ? red[t] : 0.f;
#pragma unroll
        for (int o = 4; o; o >>= 1) x += __shfl_xor_sync(~0u, x, o);
        if (t == 0) s_mean = x * (1.f/DM_);
    }
    __syncthreads();
    float mean = s_mean;
    float q = 0.f;
#pragma unroll
    for (int i = 0; i < 4; i++) { float d = v[i] - mean; q += d * d; }
#pragma unroll
    for (int o = 16; o; o >>= 1) q += __shfl_xor_sync(~0u, q, o);
    if ((t & 31) == 0) red[t >> 5] = q;
    __syncthreads();
    if (t < 32) {
        float x = (t < 8) ? red[t] : 0.f;
#pragma unroll
        for (int o = 4; o; o >>= 1) x += __shfl_xor_sync(~0u, x, o);
        if (t == 0) s_rstd = rsqrtf(x * (1.f/DM_) + 1e-5f);
    }
    __syncthreads();
    float r = s_rstd;
    float* dst = out + (long)row * ostride;
#pragma unroll
    for (int i = 0; i < 4; i++) {
        int idx = t + i*256;
        dst[idx] = (v[i] - mean) * r * w[idx] + bb[idx];
    }
}

// ---------------- tf32 helpers ----------------
__device__ __forceinline__ unsigned f2tf(float f) {
    unsigned r;
    asm("cvt.rna.tf32.f32 %0, %1;" : "=r"(r) : "f"(f));
    return r;
}

// packed {hi, lo}: hi = tf32(f); lo = tf32(f - hi)
__device__ __forceinline__ uint2 split_tf32(float f) {
    unsigned h = f2tf(f);
    return make_uint2(h, f2tf(f - __uint_as_float(h)));
}

__device__ __forceinline__ void mma_tf32(float* c, const unsigned* a, const unsigned* b) {
    asm volatile(
        "mma.sync.aligned.m16n8k8.row.col.f32.tf32.tf32.f32 "
        "{%0,%1,%2,%3}, {%4,%5,%6,%7}, {%8,%9}, {%0,%1,%2,%3};"
        : "+f"(c[0]), "+f"(c[1]), "+f"(c[2]), "+f"(c[3])
        : "r"(a[0]), "r"(a[1]), "r"(a[2]), "r"(a[3]), "r"(b[0]), "r"(b[1]));
}

// ---------------- 3xTF32 tensor-core GEMM: C[m,n] = sum_k A[m,k]*W[n,k] ----------------
// 128x128x16 tiles, 256 threads (8 warps, 2x4 warp grid, 64x32 warp tile).
// hi/lo packed as uint2 in smem (LDS.64), double-buffered stages, 1 sync/kt.
// acc += Ah*Bh + Ah*Bl + Al*Bh.
__global__ __launch_bounds__(256, 2)
void gemm_3xtf32(int M, int N, int Kd,
                 const float* __restrict__ A, int lda,
                 const float* __restrict__ W, int ldb,
                 float* __restrict__ C, int ldc,
                 const float* __restrict__ bias,
                 const float* __restrict__ add, int ldadd,
                 int act) {
    extern __shared__ uint2 sm[];
    uint2* A2 = sm;               // [2][STG]
    uint2* B2 = sm + 2*STG;       // [2][STG]

    int tid = threadIdx.x;
    int lane = tid & 31, wid = tid >> 5;
    int warpM = (wid >> 2) * 64;      // 0 or 64
    int warpN = (wid & 3) * 32;       // 0,32,64,96
    int grp = lane >> 2, thr4 = lane & 3;

    // global load mapping: each thread loads 2 float4 per matrix per stage (64 rows x 16 cols)
    int r0 = tid >> 2;                // 0..63
    int c4 = (tid & 3) * 4;           // 0,4,8,12
    int gAr0 = blockIdx.y * BM + r0, gAr1 = gAr0 + 64;
    int gBr0 = blockIdx.x * BN + r0, gBr1 = gBr0 + 64;
    bool aOK0 = gAr0 < M, aOK1 = gAr1 < M;
    bool bOK0 = gBr0 < N, bOK1 = gBr1 < N;
    const float* Ap0 = A + (long)gAr0 * lda + c4;
    const float* Ap1 = A + (long)gAr1 * lda + c4;
    const float* Wp0 = W + (long)gBr0 * ldb + c4;
    const float* Wp1 = W + (long)gBr1 * ldb + c4;

    float acc[4][4][4];
#pragma unroll
    for (int i = 0; i < 4; i++)
#pragma unroll
        for (int j = 0; j < 4; j++)
#pragma unroll
            for (int q = 0; q < 4; q++) acc[i][j][q] = 0.f;

    const float4 z4 = make_float4(0,0,0,0);
    float4 av0, av1, bv0, bv1;

    // preload + deposit stage 0
    av0 = aOK0 ? *(const float4*)(Ap0) : z4;
    av1 = aOK1 ? *(const float4*)(Ap1) : z4;
    bv0 = bOK0 ? *(const float4*)(Wp0) : z4;
    bv1 = bOK1 ? *(const float4*)(Wp1) : z4;
    {
        uint2* as = A2; uint2* bs = B2;
        as[(c4+0)*SSTA + r0] = split_tf32(av0.x);
        as[(c4+1)*SSTA + r0] = split_tf32(av0.y);
        as[(c4+2)*SSTA + r0] = split_tf32(av0.z);
        as[(c4+3)*SSTA + r0] = split_tf32(av0.w);
        as[(c4+0)*SSTA + r0+64] = split_tf32(av1.x);
        as[(c4+1)*SSTA + r0+64] = split_tf32(av1.y);
        as[(c4+2)*SSTA + r0+64] = split_tf32(av1.z);
        as[(c4+3)*SSTA + r0+64] = split_tf32(av1.w);
        bs[(c4+0)*SSTA + r0] = split_tf32(bv0.x);
        bs[(c4+1)*SSTA + r0] = split_tf32(bv0.y);
        bs[(c4+2)*SSTA + r0] = split_tf32(bv0.z);
        bs[(c4+3)*SSTA + r0] = split_tf32(bv0.w);
        bs[(c4+0)*SSTA + r0+64] = split_tf32(bv1.x);
        bs[(c4+1)*SSTA + r0+64] = split_tf32(bv1.y);
        bs[(c4+2)*SSTA + r0+64] = split_tf32(bv1.z);
        bs[(c4+3)*SSTA + r0+64] = split_tf32(bv1.w);
    }
    __syncthreads();

    int nst = Kd / BK;
    for (int kt = 0; kt < nst; kt++) {
        int cur = kt & 1;
        bool pf = (kt + 1) < nst;
        if (pf) {
            int k0 = (kt + 1) * BK;
            av0 = aOK0 ? *(const float4*)(Ap0 + k0) : z4;
            av1 = aOK1 ? *(const float4*)(Ap1 + k0) : z4;
            bv0 = bOK0 ? *(const float4*)(Wp0 + k0) : z4;
            bv1 = bOK1 ? *(const float4*)(Wp1 + k0) : z4;
        }
        const uint2* as = A2 + cur*STG;
        const uint2* bs = B2 + cur*STG;
#pragma unroll
        for (int ks = 0; ks < 2; ks++) {
            int krow = ks*8 + thr4;
            // B fragments for all j (packed hi/lo)
            uint2 b0[4], b1[4];
#pragma unroll
            for (int j = 0; j < 4; j++) {
                int n = warpN + j*8 + grp;
                b0[j] = bs[krow*SSTA + n];
                b1[j] = bs[(krow+4)*SSTA + n];
            }
#pragma unroll
            for (int i = 0; i < 4; i++) {
                int m = warpM + i*16 + grp;
                uint2 a0 = as[krow*SSTA + m];
                uint2 a1 = as[krow*SSTA + m + 8];
                uint2 a2 = as[(krow+4)*SSTA + m];
                uint2 a3 = as[(krow+4)*SSTA + m + 8];
                unsigned ah[4] = {a0.x, a1.x, a2.x, a3.x};
                unsigned al[4] = {a0.y, a1.y, a2.y, a3.y};
#pragma unroll
                for (int j = 0; j < 4; j++) {
                    unsigned bh[2] = {b0[j].x, b1[j].x};
                    mma_tf32(acc[i][j], ah, bh);           // hi*hi
                }
#pragma unroll
                for (int j = 0; j < 4; j++) {
                    unsigned bl[2] = {b0[j].y, b1[j].y};
                    mma_tf32(acc[i][j], ah, bl);           // hi*lo
                }
#pragma unroll
                for (int j = 0; j < 4; j++) {
                    unsigned bh[2] = {b0[j].x, b1[j].x};
                    mma_tf32(acc[i][j], al, bh);           // lo*hi
                }
            }
        }
        if (pf) {
            int nxt = cur ^ 1;
            uint2* asw = A2 + nxt*STG;
            uint2* bsw = B2 + nxt*STG;
            asw[(c4+0)*SSTA + r0] = split_tf32(av0.x);
            asw[(c4+1)*SSTA + r0] = split_tf32(av0.y);
            asw[(c4+2)*SSTA + r0] = split_tf32(av0.z);
            asw[(c4+3)*SSTA + r0] = split_tf32(av0.w);
            asw[(c4+0)*SSTA + r0+64] = split_tf32(av1.x);
            asw[(c4+1)*SSTA + r0+64] = split_tf32(av1.y);
            asw[(c4+2)*SSTA + r0+64] = split_tf32(av1.z);
            asw[(c4+3)*SSTA + r0+64] = split_tf32(av1.w);
            bsw[(c4+0)*SSTA + r0] = split_tf32(bv0.x);
            bsw[(c4+1)*SSTA + r0] = split_tf32(bv0.y);
            bsw[(c4+2)*SSTA + r0] = split_tf32(bv0.z);
            bsw[(c4+3)*SSTA + r0] = split_tf32(bv0.w);
            bsw[(c4+0)*SSTA + r0+64] = split_tf32(bv1.x);
            bsw[(c4+1)*SSTA + r0+64] = split_tf32(bv1.y);
            bsw[(c4+2)*SSTA + r0+64] = split_tf32(bv1.z);
            bsw[(c4+3)*SSTA + r0+64] = split_tf32(bv1.w);
            __syncthreads();
        }
    }

    // epilogue
#pragma unroll
    for (int i = 0; i < 4; i++) {
        int gm0 = blockIdx.y * BM + warpM + i*16 + grp;
#pragma unroll
        for (int j = 0; j < 4; j++) {
            int gn = blockIdx.x * BN + warpN + j*8 + 2*thr4;
#pragma unroll
            for (int half = 0; half < 2; half++) {
                int gm = gm0 + half*8;
                if (gm >= M) continue;
#pragma unroll
                for (int q = 0; q < 2; q++) {
                    int n = gn + q;
                    if (n >= N) continue;
                    float v = acc[i][j][half*2 + q];
                    if (bias) v += bias[n];
                    if (act == 1) v = (v > 20.f) ? v : log1pf(expf(v));
                    if (add) v += add[(long)gm * ldadd + n];
                    C[(long)gm * ldc + n] = v;
                }
            }
        }
    }
}

// ---------------- causal depthwise conv (K=4) + SiLU ----------------
__global__ void conv_silu_k(const float* __restrict__ xz, const float* __restrict__ cw,
                            const float* __restrict__ cb, float* __restrict__ xb) {
    long idx = (long)blockIdx.x * 256 + threadIdx.x;
    int d = idx & (DI_ - 1);
    long bl = idx >> 11;
    int l = (int)(bl & (L_ - 1));
    float acc = cb[d];
#pragma unroll
    for (int k = 0; k < K_; k++) {
        int lp = l + k - (K_ - 1);
        if (lp >= 0)
            acc = fmaf(cw[d*K_ + k], xz[(bl + (k - (K_-1))) * (2*DI_) + d], acc);
    }
    acc = acc / (1.f + expf(-acc));
    xb[idx] = acc;
}

// ---------------- selective SSM scan + D skip + z-gating ----------------
__global__ void ssm_scan_k(const float* __restrict__ xb, const float* __restrict__ xp,
                           const float* __restrict__ dl, const float* __restrict__ xz,
                           const float* __restrict__ Alog, const float* __restrict__ Dp,
                           float* __restrict__ y) {
    int t = threadIdx.x;
    int g = t >> 4, lane = t & 15;
    int ch = blockIdx.x * 16 + g;
    int b = ch >> 11;
    int d = ch & (DI_ - 1);
    float A = -expf(Alog[d*N_ + lane]);
    float Dv = Dp[d];
    float h = 0.f;
    long rowbase = (long)b * L_;
    for (int l = 0; l < L_; l++) {
        long r = rowbase + l;
        float dv = dl[r*DI_ + d];
        float xv = xb[r*DI_ + d];
        float Bv = xp[r*XPW_ + DTR_ + lane];
        float Cv = xp[r*XPW_ + DTR_ + N_ + lane];
        h = fmaf(expf(dv * A), h, dv * Bv * xv);
        float c = h * Cv;
        c += __shfl_xor_sync(~0u, c, 8);
        c += __shfl_xor_sync(~0u, c, 4);
        c += __shfl_xor_sync(~0u, c, 2);
        c += __shfl_xor_sync(~0u, c, 1);
        if (lane == 0) {
            float z = xz[r*(2*DI_) + DI_ + d];
            float yv = c + xv * Dv;
            y[r*DI_ + d] = yv * (z / (1.f + expf(-z)));
        }
    }
}

// ---------------- head ----------------
__global__ void head_k(const float* __restrict__ fin, const float* __restrict__ hw,
                       float* __restrict__ out) {
    int wid = blockIdx.x * 8 + (threadIdx.x >> 5);
    int lane = threadIdx.x & 31;
    if (wid >= B_ * P_) return;
    int b = wid / P_, p = wid % P_;
    const float* a = fin + (long)b * DM_;
    const float* w = hw + (long)p * DM_;
    float s = 0.f;
    for (int k = lane; k < DM_; k += 32) s = fmaf(a[k], w[k], s);
#pragma unroll
    for (int o = 16; o; o >>= 1) s += __shfl_xor_sync(~0u, s, o);
    if (lane == 0) out[wid] = s;
}

// ---------------- launch ----------------
extern "C" void kernel_launch(void* const* d_in, const int* in_sizes, int n_in,
                              void* d_out, int out_size) {
    const int*   tokens    = (const int*)  d_in[0];
    const float* tok_emb   = (const float*)d_in[1];
    const float* pos_emb   = (const float*)d_in[2];
    const float* ln_w      = (const float*)d_in[3];
    const float* ln_b      = (const float*)d_in[4];
    const float* in_proj_w = (const float*)d_in[5];
    const float* conv_w    = (const float*)d_in[6];
    const float* conv_b    = (const float*)d_in[7];
    const float* xproj_w   = (const float*)d_in[8];
    const float* dt_w      = (const float*)d_in[9];
    const float* dt_b      = (const float*)d_in[10];
    const float* A_log     = (const float*)d_in[11];
    const float* D_param   = (const float*)d_in[12];
    const float* out_proj_w= (const float*)d_in[13];
    const float* fnorm_w   = (const float*)d_in[14];
    const float* fnorm_b   = (const float*)d_in[15];
    const float* head_w    = (const float*)d_in[16];
    float* out = (float*)d_out;

    // allow 67.6KB dynamic smem for the GEMM (host-side config, not a stream op)
    cudaFuncSetAttribute(gemm_3xtf32, cudaFuncAttributeMaxDynamicSharedMemorySize,
                         (int)GEMM_SMEM);

    void *ph, *px, *pxz, *pxb, *pxp, *pdl, *py, *pfin;
    cudaGetSymbolAddress(&ph,  g_h);
    cudaGetSymbolAddress(&px,  g_x);
    cudaGetSymbolAddress(&pxz, g_xz);
    cudaGetSymbolAddress(&pxb, g_xb);
    cudaGetSymbolAddress(&pxp, g_xp);
    cudaGetSymbolAddress(&pdl, g_dl);
    cudaGetSymbolAddress(&py,  g_y);
    cudaGetSymbolAddress(&pfin,g_fin);
    float* h  = (float*)ph;   float* x  = (float*)px;
    float* xz = (float*)pxz;  float* xb = (float*)pxb;
    float* xp = (float*)pxp;  float* dl = (float*)pdl;
    float* y  = (float*)py;   float* fin= (float*)pfin;

    embed_k<<<M_TOK, 256>>>(tokens, tok_emb, pos_emb, h);

    for (int i = 0; i < NL_; i++) {
        ln_k<<<M_TOK, 256>>>(h, DM_, x, DM_, ln_w + i*DM_, ln_b + i*DM_);
        // in_proj: 2048 x 4096 x 1024
        gemm_3xtf32<<<dim3(32, 16), 256, GEMM_SMEM>>>(M_TOK, 2*DI_, DM_,
            x, DM_, in_proj_w + (long)i*2*DI_*DM_, DM_,
            xz, 2*DI_, nullptr, nullptr, 0, 0);
        conv_silu_k<<<(M_TOK*DI_)/256, 256>>>(xz, conv_w + (long)i*DI_*K_, conv_b + (long)i*DI_, xb);
        // xproj: 2048 x 160 x 2048
        gemm_3xtf32<<<dim3(2, 16), 256, GEMM_SMEM>>>(M_TOK, XPW_, DI_,
            xb, DI_, xproj_w + (long)i*XPW_*DI_, DI_,
            xp, XPW_, nullptr, nullptr, 0, 0);
        // delta = softplus(dt_r @ dtw.T + dtb): 2048 x 2048 x 128
        gemm_3xtf32<<<dim3(16, 16), 256, GEMM_SMEM>>>(M_TOK, DI_, DTR_,
            xp, XPW_, dt_w + (long)i*DI_*DTR_, DTR_,
            dl, DI_, dt_b + (long)i*DI_, nullptr, 0, 1);
        ssm_scan_k<<<(B_*DI_)/16, 256>>>(xb, xp, dl, xz,
            A_log + (long)i*DI_*N_, D_param + (long)i*DI_, y);
        // out_proj + residual: 2048 x 1024 x 2048
        gemm_3xtf32<<<dim3(8, 16), 256, GEMM_SMEM>>>(M_TOK, DM_, DI_,
            y, DI_, out_proj_w + (long)i*DM_*DI_, DI_,
            h, DM_, nullptr, h, DM_, 0);
    }

    ln_k<<<B_, 256>>>(h + (long)(L_-1)*DM_, (long)L_*DM_, fin, DM_, fnorm_w, fnorm_b);
    head_k<<<P_, 256>>>(fin, head_w, out);
}

// round 5
// speedup vs baseline: 1.6942x; 1.6942x over previous
#include <cuda_runtime.h>
#include <cuda_bf16.h>
#include <math.h>

// Problem constants
#define B_  8
#define L_  256
#define DM_ 1024
#define DI_ 2048
#define N_  16
#define K_  4
#define NL_ 4
#define DTR_ 128
#define P_  97
#define M_TOK (B_*L_)          // 2048 token rows
#define XPW_ (DTR_ + 2*N_)     // 160

// GEMM tiling
#define BM 128
#define BN 128
#define BK 16
#define SST 132                // smem row stride in words ([kp][m] layout, kp = k/2)

// ---------------- scratch (static device globals; no allocation) ----------------
__device__ __align__(16) float g_h [M_TOK*DM_];
__device__ __align__(16) float g_x [M_TOK*DM_];
__device__ __align__(16) float g_xz[M_TOK*2*DI_];
__device__ __align__(16) float g_xb[M_TOK*DI_];
__device__ __align__(16) float g_xp[M_TOK*XPW_];
__device__ __align__(16) float g_dl[M_TOK*DI_];
__device__ __align__(16) float g_y [M_TOK*DI_];
__device__ __align__(16) float g_fin[B_*DM_];

// ---------------- embedding ----------------
__global__ void embed_k(const int* __restrict__ tok, const float* __restrict__ te,
                        const float* __restrict__ pe, float* __restrict__ h) {
    int row = blockIdx.x;
    int l = row & (L_ - 1);
    int t = tok[row];
    const float* tsrc = te + (long)t * DM_;
    const float* psrc = pe + (long)l * DM_;
    float* dst = h + (long)row * DM_;
    for (int d = threadIdx.x; d < DM_; d += 256)
        dst[d] = tsrc[d] + psrc[d];
}

// ---------------- layernorm ----------------
__global__ void ln_k(const float* __restrict__ in, long istride,
                     float* __restrict__ out, long ostride,
                     const float* __restrict__ w, const float* __restrict__ bb) {
    __shared__ float red[8];
    __shared__ float s_mean, s_rstd;
    int t = threadIdx.x;
    int row = blockIdx.x;
    const float* src = in + (long)row * istride;
    float v[4];
    float s = 0.f;
#pragma unroll
    for (int i = 0; i < 4; i++) { v[i] = src[t + i*256]; s += v[i]; }
#pragma unroll
    for (int o = 16; o; o >>= 1) s += __shfl_xor_sync(~0u, s, o);
    if ((t & 31) == 0) red[t >> 5] = s;
    __syncthreads();
    if (t < 32) {
        float x = (t < 8) ? red[t] : 0.f;
#pragma unroll
        for (int o = 4; o; o >>= 1) x += __shfl_xor_sync(~0u, x, o);
        if (t == 0) s_mean = x * (1.f/DM_);
    }
    __syncthreads();
    float mean = s_mean;
    float q = 0.f;
#pragma unroll
    for (int i = 0; i < 4; i++) { float d = v[i] - mean; q += d * d; }
#pragma unroll
    for (int o = 16; o; o >>= 1) q += __shfl_xor_sync(~0u, q, o);
    if ((t & 31) == 0) red[t >> 5] = q;
    __syncthreads();
    if (t < 32) {
        float x = (t < 8) ? red[t] : 0.f;
#pragma unroll
        for (int o = 4; o; o >>= 1) x += __shfl_xor_sync(~0u, x, o);
        if (t == 0) s_rstd = rsqrtf(x * (1.f/DM_) + 1e-5f);
    }
    __syncthreads();
    float r = s_rstd;
    float* dst = out + (long)row * ostride;
#pragma unroll
    for (int i = 0; i < 4; i++) {
        int idx = t + i*256;
        dst[idx] = (v[i] - mean) * r * w[idx] + bb[idx];
    }
}

// ---------------- bf16 split helpers ----------------
// For a k-pair (x = k even, y = k odd): hi word = {bf16(x), bf16(y)},
// lo word = {bf16(x - hi_x), bf16(y - hi_y)}. Low half = even k.
__device__ __forceinline__ uint2 split2_bf16(float x, float y) {
    __nv_bfloat16 hx = __float2bfloat16(x);
    __nv_bfloat16 hy = __float2bfloat16(y);
    float lx = x - __bfloat162float(hx);
    float ly = y - __bfloat162float(hy);
    __nv_bfloat162 hp = __halves2bfloat162(hx, hy);
    __nv_bfloat162 lp = __halves2bfloat162(__float2bfloat16(lx), __float2bfloat16(ly));
    unsigned hw, lw;
    hw = *reinterpret_cast<unsigned*>(&hp);
    lw = *reinterpret_cast<unsigned*>(&lp);
    return make_uint2(hw, lw);
}

__device__ __forceinline__ void mma_bf16(float* c, const unsigned* a, const unsigned* b) {
    asm volatile(
        "mma.sync.aligned.m16n8k16.row.col.f32.bf16.bf16.f32 "
        "{%0,%1,%2,%3}, {%4,%5,%6,%7}, {%8,%9}, {%0,%1,%2,%3};"
        : "+f"(c[0]), "+f"(c[1]), "+f"(c[2]), "+f"(c[3])
        : "r"(a[0]), "r"(a[1]), "r"(a[2]), "r"(a[3]), "r"(b[0]), "r"(b[1]));
}

// ---------------- bf16x2 compensated tensor-core GEMM: C[m,n] = sum_k A[m,k]*W[n,k] ----
// 128x128x16 tiles, 256 threads (8 warps, 2x4 warp grid, 64x32 warp tile).
// A = Ah+Al, B = Bh+Bl (bf16 Dekker split); acc += Ah*Bh + Ah*Bl + Al*Bh (fp32 accum).
// smem: [kp][m] words of bf16x2 (k-pair packed), single-buffered, reg prefetch.
// act: 0=none, 1=softplus. bias per-n, add per-element.
__global__ __launch_bounds__(256, 2)
void gemm_bf16c(int M, int N, int Kd,
                const float* __restrict__ A, int lda,
                const float* __restrict__ W, int ldb,
                float* __restrict__ C, int ldc,
                const float* __restrict__ bias,
                const float* __restrict__ add, int ldadd,
                int act) {
    __shared__ unsigned Ahp[8*SST], Alp[8*SST];   // 8 k-pairs x 128 m
    __shared__ unsigned Bhp[8*SST], Blp[8*SST];
    int tid = threadIdx.x;
    int lane = tid & 31, wid = tid >> 5;
    int warpM = (wid >> 2) * 64;      // 0 or 64
    int warpN = (wid & 3) * 32;       // 0,32,64,96
    int grp = lane >> 2, tig = lane & 3;

    // global load mapping: each thread loads 2 float4 per matrix per stage
    int r0 = tid >> 2;                // 0..63
    int c4 = (tid & 3) * 4;           // 0,4,8,12 (k offset)
    int kp0 = c4 >> 1;                // 0,2,4,6  (k-pair row in smem)
    int gAr0 = blockIdx.y * BM + r0, gAr1 = gAr0 + 64;
    int gBr0 = blockIdx.x * BN + r0, gBr1 = gBr0 + 64;
    bool aOK0 = gAr0 < M, aOK1 = gAr1 < M;
    bool bOK0 = gBr0 < N, bOK1 = gBr1 < N;
    const float* Ap0 = A + (long)gAr0 * lda + c4;
    const float* Ap1 = A + (long)gAr1 * lda + c4;
    const float* Wp0 = W + (long)gBr0 * ldb + c4;
    const float* Wp1 = W + (long)gBr1 * ldb + c4;

    float acc[4][4][4];
#pragma unroll
    for (int i = 0; i < 4; i++)
#pragma unroll
        for (int j = 0; j < 4; j++)
#pragma unroll
            for (int q = 0; q < 4; q++) acc[i][j][q] = 0.f;

    const float4 z4 = make_float4(0,0,0,0);
    float4 av0, av1, bv0, bv1;

    // preload stage 0 into regs
    av0 = aOK0 ? *(const float4*)(Ap0) : z4;
    av1 = aOK1 ? *(const float4*)(Ap1) : z4;
    bv0 = bOK0 ? *(const float4*)(Wp0) : z4;
    bv1 = bOK1 ? *(const float4*)(Wp1) : z4;

    int nst = Kd / BK;
    for (int kt = 0; kt < nst; kt++) {
        // deposit regs -> smem (hi/lo bf16 k-pair split)
        {
            uint2 s;
            s = split2_bf16(av0.x, av0.y); Ahp[kp0*SST + r0] = s.x; Alp[kp0*SST + r0] = s.y;
            s = split2_bf16(av0.z, av0.w); Ahp[(kp0+1)*SST + r0] = s.x; Alp[(kp0+1)*SST + r0] = s.y;
            s = split2_bf16(av1.x, av1.y); Ahp[kp0*SST + r0+64] = s.x; Alp[kp0*SST + r0+64] = s.y;
            s = split2_bf16(av1.z, av1.w); Ahp[(kp0+1)*SST + r0+64] = s.x; Alp[(kp0+1)*SST + r0+64] = s.y;
            s = split2_bf16(bv0.x, bv0.y); Bhp[kp0*SST + r0] = s.x; Blp[kp0*SST + r0] = s.y;
            s = split2_bf16(bv0.z, bv0.w); Bhp[(kp0+1)*SST + r0] = s.x; Blp[(kp0+1)*SST + r0] = s.y;
            s = split2_bf16(bv1.x, bv1.y); Bhp[kp0*SST + r0+64] = s.x; Blp[kp0*SST + r0+64] = s.y;
            s = split2_bf16(bv1.z, bv1.w); Bhp[(kp0+1)*SST + r0+64] = s.x; Blp[(kp0+1)*SST + r0+64] = s.y;
        }
        __syncthreads();

        // prefetch next stage into regs (overlaps with compute below)
        if (kt + 1 < nst) {
            int k0 = (kt + 1) * BK;
            av0 = aOK0 ? *(const float4*)(Ap0 + k0) : z4;
            av1 = aOK1 ? *(const float4*)(Ap1 + k0) : z4;
            bv0 = bOK0 ? *(const float4*)(Wp0 + k0) : z4;
            bv1 = bOK1 ? *(const float4*)(Wp1 + k0) : z4;
        }

        // compute: one m16n8k16 step covers all 16 k of this tile
        {
            unsigned bh[4][2], bl[4][2];
#pragma unroll
            for (int j = 0; j < 4; j++) {
                int n = warpN + j*8 + grp;
                bh[j][0] = Bhp[tig*SST + n];
                bh[j][1] = Bhp[(tig+4)*SST + n];
                bl[j][0] = Blp[tig*SST + n];
                bl[j][1] = Blp[(tig+4)*SST + n];
            }
#pragma unroll
            for (int i = 0; i < 4; i++) {
                int m = warpM + i*16 + grp;
                unsigned ah[4], al[4];
                ah[0] = Ahp[tig*SST + m];     ah[1] = Ahp[tig*SST + m + 8];
                ah[2] = Ahp[(tig+4)*SST + m]; ah[3] = Ahp[(tig+4)*SST + m + 8];
                al[0] = Alp[tig*SST + m];     al[1] = Alp[tig*SST + m + 8];
                al[2] = Alp[(tig+4)*SST + m]; al[3] = Alp[(tig+4)*SST + m + 8];
#pragma unroll
                for (int j = 0; j < 4; j++)
                    mma_bf16(acc[i][j], ah, bh[j]);   // hi*hi
#pragma unroll
                for (int j = 0; j < 4; j++)
                    mma_bf16(acc[i][j], ah, bl[j]);   // hi*lo
#pragma unroll
                for (int j = 0; j < 4; j++)
                    mma_bf16(acc[i][j], al, bh[j]);   // lo*hi
            }
        }
        __syncthreads();
    }

    // epilogue (c-fragment layout: rows grp/grp+8, cols 2*tig, 2*tig+1)
#pragma unroll
    for (int i = 0; i < 4; i++) {
        int gm0 = blockIdx.y * BM + warpM + i*16 + grp;
#pragma unroll
        for (int j = 0; j < 4; j++) {
            int gn = blockIdx.x * BN + warpN + j*8 + 2*tig;
#pragma unroll
            for (int half = 0; half < 2; half++) {
                int gm = gm0 + half*8;
                if (gm >= M) continue;
#pragma unroll
                for (int q = 0; q < 2; q++) {
                    int n = gn + q;
                    if (n >= N) continue;
                    float v = acc[i][j][half*2 + q];
                    if (bias) v += bias[n];
                    if (act == 1) v = (v > 20.f) ? v : log1pf(expf(v));
                    if (add) v += add[(long)gm * ldadd + n];
                    C[(long)gm * ldc + n] = v;
                }
            }
        }
    }
}

// ---------------- causal depthwise conv (K=4) + SiLU ----------------
__global__ void conv_silu_k(const float* __restrict__ xz, const float* __restrict__ cw,
                            const float* __restrict__ cb, float* __restrict__ xb) {
    long idx = (long)blockIdx.x * 256 + threadIdx.x;
    int d = idx & (DI_ - 1);
    long bl = idx >> 11;
    int l = (int)(bl & (L_ - 1));
    float acc = cb[d];
#pragma unroll
    for (int k = 0; k < K_; k++) {
        int lp = l + k - (K_ - 1);
        if (lp >= 0)
            acc = fmaf(cw[d*K_ + k], xz[(bl + (k - (K_-1))) * (2*DI_) + d], acc);
    }
    acc = acc / (1.f + expf(-acc));
    xb[idx] = acc;
}

// ---------------- selective SSM scan + D skip + z-gating ----------------
__global__ void ssm_scan_k(const float* __restrict__ xb, const float* __restrict__ xp,
                           const float* __restrict__ dl, const float* __restrict__ xz,
                           const float* __restrict__ Alog, const float* __restrict__ Dp,
                           float* __restrict__ y) {
    int t = threadIdx.x;
    int g = t >> 4, lane = t & 15;
    int ch = blockIdx.x * 16 + g;
    int b = ch >> 11;
    int d = ch & (DI_ - 1);
    float A = -expf(Alog[d*N_ + lane]);
    float Dv = Dp[d];
    float h = 0.f;
    long rowbase = (long)b * L_;
    for (int l = 0; l < L_; l++) {
        long r = rowbase + l;
        float dv = dl[r*DI_ + d];
        float xv = xb[r*DI_ + d];
        float Bv = xp[r*XPW_ + DTR_ + lane];
        float Cv = xp[r*XPW_ + DTR_ + N_ + lane];
        h = fmaf(expf(dv * A), h, dv * Bv * xv);
        float c = h * Cv;
        c += __shfl_xor_sync(~0u, c, 8);
        c += __shfl_xor_sync(~0u, c, 4);
        c += __shfl_xor_sync(~0u, c, 2);
        c += __shfl_xor_sync(~0u, c, 1);
        if (lane == 0) {
            float z = xz[r*(2*DI_) + DI_ + d];
            float yv = c + xv * Dv;
            y[r*DI_ + d] = yv * (z / (1.f + expf(-z)));
        }
    }
}

// ---------------- head ----------------
__global__ void head_k(const float* __restrict__ fin, const float* __restrict__ hw,
                       float* __restrict__ out) {
    int wid = blockIdx.x * 8 + (threadIdx.x >> 5);
    int lane = threadIdx.x & 31;
    if (wid >= B_ * P_) return;
    int b = wid / P_, p = wid % P_;
    const float* a = fin + (long)b * DM_;
    const float* w = hw + (long)p * DM_;
    float s = 0.f;
    for (int k = lane; k < DM_; k += 32) s = fmaf(a[k], w[k], s);
#pragma unroll
    for (int o = 16; o; o >>= 1) s += __shfl_xor_sync(~0u, s, o);
    if (lane == 0) out[wid] = s;
}

// ---------------- launch ----------------
extern "C" void kernel_launch(void* const* d_in, const int* in_sizes, int n_in,
                              void* d_out, int out_size) {
    const int*   tokens    = (const int*)  d_in[0];
    const float* tok_emb   = (const float*)d_in[1];
    const float* pos_emb   = (const float*)d_in[2];
    const float* ln_w      = (const float*)d_in[3];
    const float* ln_b      = (const float*)d_in[4];
    const float* in_proj_w = (const float*)d_in[5];
    const float* conv_w    = (const float*)d_in[6];
    const float* conv_b    = (const float*)d_in[7];
    const float* xproj_w   = (const float*)d_in[8];
    const float* dt_w      = (const float*)d_in[9];
    const float* dt_b      = (const float*)d_in[10];
    const float* A_log     = (const float*)d_in[11];
    const float* D_param   = (const float*)d_in[12];
    const float* out_proj_w= (const float*)d_in[13];
    const float* fnorm_w   = (const float*)d_in[14];
    const float* fnorm_b   = (const float*)d_in[15];
    const float* head_w    = (const float*)d_in[16];
    float* out = (float*)d_out;

    void *ph, *px, *pxz, *pxb, *pxp, *pdl, *py, *pfin;
    cudaGetSymbolAddress(&ph,  g_h);
    cudaGetSymbolAddress(&px,  g_x);
    cudaGetSymbolAddress(&pxz, g_xz);
    cudaGetSymbolAddress(&pxb, g_xb);
    cudaGetSymbolAddress(&pxp, g_xp);
    cudaGetSymbolAddress(&pdl, g_dl);
    cudaGetSymbolAddress(&py,  g_y);
    cudaGetSymbolAddress(&pfin,g_fin);
    float* h  = (float*)ph;   float* x  = (float*)px;
    float* xz = (float*)pxz;  float* xb = (float*)pxb;
    float* xp = (float*)pxp;  float* dl = (float*)pdl;
    float* y  = (float*)py;   float* fin= (float*)pfin;

    embed_k<<<M_TOK, 256>>>(tokens, tok_emb, pos_emb, h);

    for (int i = 0; i < NL_; i++) {
        ln_k<<<M_TOK, 256>>>(h, DM_, x, DM_, ln_w + i*DM_, ln_b + i*DM_);
        // in_proj: 2048 x 4096 x 1024
        gemm_bf16c<<<dim3(32, 16), 256>>>(M_TOK, 2*DI_, DM_,
            x, DM_, in_proj_w + (long)i*2*DI_*DM_, DM_,
            xz, 2*DI_, nullptr, nullptr, 0, 0);
        conv_silu_k<<<(M_TOK*DI_)/256, 256>>>(xz, conv_w + (long)i*DI_*K_, conv_b + (long)i*DI_, xb);
        // xproj: 2048 x 160 x 2048
        gemm_bf16c<<<dim3(2, 16), 256>>>(M_TOK, XPW_, DI_,
            xb, DI_, xproj_w + (long)i*XPW_*DI_, DI_,
            xp, XPW_, nullptr, nullptr, 0, 0);
        // delta = softplus(dt_r @ dtw.T + dtb): 2048 x 2048 x 128
        gemm_bf16c<<<dim3(16, 16), 256>>>(M_TOK, DI_, DTR_,
            xp, XPW_, dt_w + (long)i*DI_*DTR_, DTR_,
            dl, DI_, dt_b + (long)i*DI_, nullptr, 0, 1);
        ssm_scan_k<<<(B_*DI_)/16, 256>>>(xb, xp, dl, xz,
            A_log + (long)i*DI_*N_, D_param + (long)i*DI_, y);
        // out_proj + residual: 2048 x 1024 x 2048
        gemm_bf16c<<<dim3(8, 16), 256>>>(M_TOK, DM_, DI_,
            y, DI_, out_proj_w + (long)i*DM_*DI_, DI_,
            h, DM_, nullptr, h, DM_, 0);
    }

    ln_k<<<B_, 256>>>(h + (long)(L_-1)*DM_, (long)L_*DM_, fin, DM_, fnorm_w, fnorm_b);
    head_k<<<P_, 256>>>(fin, head_w, out);
}

// round 6
// speedup vs baseline: 2.0607x; 1.2164x over previous
#include <cuda_runtime.h>
#include <cuda_bf16.h>
#include <math.h>

// Problem constants
#define B_  8
#define L_  256
#define DM_ 1024
#define DI_ 2048
#define N_  16
#define K_  4
#define NL_ 4
#define DTR_ 128
#define P_  97
#define M_TOK (B_*L_)          // 2048 token rows
#define XPW_ (DTR_ + 2*N_)     // 160

// GEMM tiling
#define BM 128
#define BN 128
#define BK 16
#define SST 132                // smem row stride in words ([kp][m] layout, kp = k/2)

// ---------------- scratch (static device globals; no allocation) ----------------
__device__ __align__(16) float g_h [M_TOK*DM_];
__device__ __align__(16) float g_x [M_TOK*DM_];
__device__ __align__(16) float g_xz[M_TOK*2*DI_];
__device__ __align__(16) float g_xb[M_TOK*DI_];
__device__ __align__(16) float g_xp[M_TOK*XPW_];
__device__ __align__(16) float g_dl[M_TOK*DI_];
__device__ __align__(16) float g_y [M_TOK*DI_];
__device__ __align__(16) float g_fin[B_*DM_];

// ---------------- small utils ----------------
__global__ void zero_k(float* __restrict__ p, int n4) {
    int i = blockIdx.x * 256 + threadIdx.x;
    if (i < n4) reinterpret_cast<float4*>(p)[i] = make_float4(0,0,0,0);
}

// ---------------- embedding ----------------
__global__ void embed_k(const int* __restrict__ tok, const float* __restrict__ te,
                        const float* __restrict__ pe, float* __restrict__ h) {
    int row = blockIdx.x;
    int l = row & (L_ - 1);
    int t = tok[row];
    const float* tsrc = te + (long)t * DM_;
    const float* psrc = pe + (long)l * DM_;
    float* dst = h + (long)row * DM_;
    for (int d = threadIdx.x; d < DM_; d += 256)
        dst[d] = tsrc[d] + psrc[d];
}

// ---------------- layernorm ----------------
__global__ void ln_k(const float* __restrict__ in, long istride,
                     float* __restrict__ out, long ostride,
                     const float* __restrict__ w, const float* __restrict__ bb) {
    __shared__ float red[8];
    __shared__ float s_mean, s_rstd;
    int t = threadIdx.x;
    int row = blockIdx.x;
    const float* src = in + (long)row * istride;
    float v[4];
    float s = 0.f;
#pragma unroll
    for (int i = 0; i < 4; i++) { v[i] = src[t + i*256]; s += v[i]; }
#pragma unroll
    for (int o = 16; o; o >>= 1) s += __shfl_xor_sync(~0u, s, o);
    if ((t & 31) == 0) red[t >> 5] = s;
    __syncthreads();
    if (t < 32) {
        float x = (t < 8) ? red[t] : 0.f;
#pragma unroll
        for (int o = 4; o; o >>= 1) x += __shfl_xor_sync(~0u, x, o);
        if (t == 0) s_mean = x * (1.f/DM_);
    }
    __syncthreads();
    float mean = s_mean;
    float q = 0.f;
#pragma unroll
    for (int i = 0; i < 4; i++) { float d = v[i] - mean; q += d * d; }
#pragma unroll
    for (int o = 16; o; o >>= 1) q += __shfl_xor_sync(~0u, q, o);
    if ((t & 31) == 0) red[t >> 5] = q;
    __syncthreads();
    if (t < 32) {
        float x = (t < 8) ? red[t] : 0.f;
#pragma unroll
        for (int o = 4; o; o >>= 1) x += __shfl_xor_sync(~0u, x, o);
        if (t == 0) s_rstd = rsqrtf(x * (1.f/DM_) + 1e-5f);
    }
    __syncthreads();
    float r = s_rstd;
    float* dst = out + (long)row * ostride;
#pragma unroll
    for (int i = 0; i < 4; i++) {
        int idx = t + i*256;
        dst[idx] = (v[i] - mean) * r * w[idx] + bb[idx];
    }
}

// ---------------- bf16 split helpers ----------------
__device__ __forceinline__ uint2 split2_bf16(float x, float y) {
    __nv_bfloat16 hx = __float2bfloat16(x);
    __nv_bfloat16 hy = __float2bfloat16(y);
    float lx = x - __bfloat162float(hx);
    float ly = y - __bfloat162float(hy);
    __nv_bfloat162 hp = __halves2bfloat162(hx, hy);
    __nv_bfloat162 lp = __halves2bfloat162(__float2bfloat16(lx), __float2bfloat16(ly));
    unsigned hw, lw;
    hw = *reinterpret_cast<unsigned*>(&hp);
    lw = *reinterpret_cast<unsigned*>(&lp);
    return make_uint2(hw, lw);
}

__device__ __forceinline__ void mma_bf16(float* c, const unsigned* a, const unsigned* b) {
    asm volatile(
        "mma.sync.aligned.m16n8k16.row.col.f32.bf16.bf16.f32 "
        "{%0,%1,%2,%3}, {%4,%5,%6,%7}, {%8,%9}, {%0,%1,%2,%3};"
        : "+f"(c[0]), "+f"(c[1]), "+f"(c[2]), "+f"(c[3])
        : "r"(a[0]), "r"(a[1]), "r"(a[2]), "r"(a[3]), "r"(b[0]), "r"(b[1]));
}

// shared compute body macro: one 128x128x16 step from buffer `cur`
#define GEMM_DEPOSIT(AH, AL, BH, BL)                                                   \
    {                                                                                  \
        uint2 s;                                                                       \
        s = split2_bf16(av0.x, av0.y); AH[kp0*SST + r0] = s.x; AL[kp0*SST + r0] = s.y; \
        s = split2_bf16(av0.z, av0.w); AH[(kp0+1)*SST + r0] = s.x; AL[(kp0+1)*SST + r0] = s.y; \
        s = split2_bf16(av1.x, av1.y); AH[kp0*SST + r0+64] = s.x; AL[kp0*SST + r0+64] = s.y; \
        s = split2_bf16(av1.z, av1.w); AH[(kp0+1)*SST + r0+64] = s.x; AL[(kp0+1)*SST + r0+64] = s.y; \
        s = split2_bf16(bv0.x, bv0.y); BH[kp0*SST + r0] = s.x; BL[kp0*SST + r0] = s.y; \
        s = split2_bf16(bv0.z, bv0.w); BH[(kp0+1)*SST + r0] = s.x; BL[(kp0+1)*SST + r0] = s.y; \
        s = split2_bf16(bv1.x, bv1.y); BH[kp0*SST + r0+64] = s.x; BL[kp0*SST + r0+64] = s.y; \
        s = split2_bf16(bv1.z, bv1.w); BH[(kp0+1)*SST + r0+64] = s.x; BL[(kp0+1)*SST + r0+64] = s.y; \
    }

#define GEMM_COMPUTE(AH, AL, BH, BL)                                                   \
    {                                                                                  \
        unsigned bh[4][2], bl[4][2];                                                   \
        _Pragma("unroll")                                                              \
        for (int j = 0; j < 4; j++) {                                                  \
            int n = warpN + j*8 + grp;                                                 \
            bh[j][0] = BH[tig*SST + n];                                                \
            bh[j][1] = BH[(tig+4)*SST + n];                                            \
            bl[j][0] = BL[tig*SST + n];                                                \
            bl[j][1] = BL[(tig+4)*SST + n];                                            \
        }                                                                              \
        _Pragma("unroll")                                                              \
        for (int i = 0; i < 4; i++) {                                                  \
            int m = warpM + i*16 + grp;                                                \
            unsigned ah[4], al[4];                                                     \
            ah[0] = AH[tig*SST + m];     ah[1] = AH[tig*SST + m + 8];                  \
            ah[2] = AH[(tig+4)*SST + m]; ah[3] = AH[(tig+4)*SST + m + 8];              \
            al[0] = AL[tig*SST + m];     al[1] = AL[tig*SST + m + 8];                  \
            al[2] = AL[(tig+4)*SST + m]; al[3] = AL[(tig+4)*SST + m + 8];              \
            _Pragma("unroll")                                                          \
            for (int j = 0; j < 4; j++) mma_bf16(acc[i][j], ah, bh[j]);                \
            _Pragma("unroll")                                                          \
            for (int j = 0; j < 4; j++) mma_bf16(acc[i][j], ah, bl[j]);                \
            _Pragma("unroll")                                                          \
            for (int j = 0; j < 4; j++) mma_bf16(acc[i][j], al, bh[j]);                \
        }                                                                              \
    }

// ---------------- bf16x2 compensated GEMM (double-buffered): C = A @ W^T ----------------
__global__ __launch_bounds__(256, 2)
void gemm_bf16c(int M, int N, int Kd,
                const float* __restrict__ A, int lda,
                const float* __restrict__ W, int ldb,
                float* __restrict__ C, int ldc,
                const float* __restrict__ bias,
                const float* __restrict__ add, int ldadd,
                int act) {
    __shared__ unsigned Ahp[2][8*SST], Alp[2][8*SST];
    __shared__ unsigned Bhp[2][8*SST], Blp[2][8*SST];
    int tid = threadIdx.x;
    int lane = tid & 31, wid = tid >> 5;
    int warpM = (wid >> 2) * 64;
    int warpN = (wid & 3) * 32;
    int grp = lane >> 2, tig = lane & 3;

    int r0 = tid >> 2;
    int c4 = (tid & 3) * 4;
    int kp0 = c4 >> 1;
    int gAr0 = blockIdx.y * BM + r0, gAr1 = gAr0 + 64;
    int gBr0 = blockIdx.x * BN + r0, gBr1 = gBr0 + 64;
    bool aOK0 = gAr0 < M, aOK1 = gAr1 < M;
    bool bOK0 = gBr0 < N, bOK1 = gBr1 < N;
    const float* Ap0 = A + (long)gAr0 * lda + c4;
    const float* Ap1 = A + (long)gAr1 * lda + c4;
    const float* Wp0 = W + (long)gBr0 * ldb + c4;
    const float* Wp1 = W + (long)gBr1 * ldb + c4;

    float acc[4][4][4];
#pragma unroll
    for (int i = 0; i < 4; i++)
#pragma unroll
        for (int j = 0; j < 4; j++)
#pragma unroll
            for (int q = 0; q < 4; q++) acc[i][j][q] = 0.f;

    const float4 z4 = make_float4(0,0,0,0);
    float4 av0, av1, bv0, bv1;

    av0 = aOK0 ? *(const float4*)(Ap0) : z4;
    av1 = aOK1 ? *(const float4*)(Ap1) : z4;
    bv0 = bOK0 ? *(const float4*)(Wp0) : z4;
    bv1 = bOK1 ? *(const float4*)(Wp1) : z4;
    GEMM_DEPOSIT(Ahp[0], Alp[0], Bhp[0], Blp[0]);
    __syncthreads();

    int nst = Kd / BK;
    for (int kt = 0; kt < nst; kt++) {
        int cur = kt & 1;
        bool pf = (kt + 1) < nst;
        if (pf) {
            int k0 = (kt + 1) * BK;
            av0 = aOK0 ? *(const float4*)(Ap0 + k0) : z4;
            av1 = aOK1 ? *(const float4*)(Ap1 + k0) : z4;
            bv0 = bOK0 ? *(const float4*)(Wp0 + k0) : z4;
            bv1 = bOK1 ? *(const float4*)(Wp1 + k0) : z4;
        }
        if (cur == 0) { GEMM_COMPUTE(Ahp[0], Alp[0], Bhp[0], Blp[0]); }
        else          { GEMM_COMPUTE(Ahp[1], Alp[1], Bhp[1], Blp[1]); }
        if (pf) {
            if (cur == 0) { GEMM_DEPOSIT(Ahp[1], Alp[1], Bhp[1], Blp[1]); }
            else          { GEMM_DEPOSIT(Ahp[0], Alp[0], Bhp[0], Blp[0]); }
            __syncthreads();
        }
    }

#pragma unroll
    for (int i = 0; i < 4; i++) {
        int gm0 = blockIdx.y * BM + warpM + i*16 + grp;
#pragma unroll
        for (int j = 0; j < 4; j++) {
            int gn = blockIdx.x * BN + warpN + j*8 + 2*tig;
#pragma unroll
            for (int half = 0; half < 2; half++) {
                int gm = gm0 + half*8;
                if (gm >= M) continue;
#pragma unroll
                for (int q = 0; q < 2; q++) {
                    int n = gn + q;
                    if (n >= N) continue;
                    float v = acc[i][j][half*2 + q];
                    if (bias) v += bias[n];
                    if (act == 1) v = (v > 20.f) ? v : log1pf(expf(v));
                    if (add) v += add[(long)gm * ldadd + n];
                    C[(long)gm * ldc + n] = v;
                }
            }
        }
    }
}

// ---------------- split-K variant: C += partial (atomicAdd epilogue) ----------------
// blockIdx.z = split index; each split covers kcnt contiguous k.
__global__ __launch_bounds__(256, 2)
void gemm_bf16c_sk(int M, int N, int kcnt,
                   const float* __restrict__ A, int lda,
                   const float* __restrict__ W, int ldb,
                   float* __restrict__ C, int ldc) {
    __shared__ unsigned Ahp[2][8*SST], Alp[2][8*SST];
    __shared__ unsigned Bhp[2][8*SST], Blp[2][8*SST];
    int tid = threadIdx.x;
    int lane = tid & 31, wid = tid >> 5;
    int warpM = (wid >> 2) * 64;
    int warpN = (wid & 3) * 32;
    int grp = lane >> 2, tig = lane & 3;

    long kbeg = (long)blockIdx.z * kcnt;
    A += kbeg; W += kbeg;

    int r0 = tid >> 2;
    int c4 = (tid & 3) * 4;
    int kp0 = c4 >> 1;
    int gAr0 = blockIdx.y * BM + r0, gAr1 = gAr0 + 64;
    int gBr0 = blockIdx.x * BN + r0, gBr1 = gBr0 + 64;
    bool aOK0 = gAr0 < M, aOK1 = gAr1 < M;
    bool bOK0 = gBr0 < N, bOK1 = gBr1 < N;
    const float* Ap0 = A + (long)gAr0 * lda + c4;
    const float* Ap1 = A + (long)gAr1 * lda + c4;
    const float* Wp0 = W + (long)gBr0 * ldb + c4;
    const float* Wp1 = W + (long)gBr1 * ldb + c4;

    float acc[4][4][4];
#pragma unroll
    for (int i = 0; i < 4; i++)
#pragma unroll
        for (int j = 0; j < 4; j++)
#pragma unroll
            for (int q = 0; q < 4; q++) acc[i][j][q] = 0.f;

    const float4 z4 = make_float4(0,0,0,0);
    float4 av0, av1, bv0, bv1;

    av0 = aOK0 ? *(const float4*)(Ap0) : z4;
    av1 = aOK1 ? *(const float4*)(Ap1) : z4;
    bv0 = bOK0 ? *(const float4*)(Wp0) : z4;
    bv1 = bOK1 ? *(const float4*)(Wp1) : z4;
    GEMM_DEPOSIT(Ahp[0], Alp[0], Bhp[0], Blp[0]);
    __syncthreads();

    int nst = kcnt / BK;
    for (int kt = 0; kt < nst; kt++) {
        int cur = kt & 1;
        bool pf = (kt + 1) < nst;
        if (pf) {
            int k0 = (kt + 1) * BK;
            av0 = aOK0 ? *(const float4*)(Ap0 + k0) : z4;
            av1 = aOK1 ? *(const float4*)(Ap1 + k0) : z4;
            bv0 = bOK0 ? *(const float4*)(Wp0 + k0) : z4;
            bv1 = bOK1 ? *(const float4*)(Wp1 + k0) : z4;
        }
        if (cur == 0) { GEMM_COMPUTE(Ahp[0], Alp[0], Bhp[0], Blp[0]); }
        else          { GEMM_COMPUTE(Ahp[1], Alp[1], Bhp[1], Blp[1]); }
        if (pf) {
            if (cur == 0) { GEMM_DEPOSIT(Ahp[1], Alp[1], Bhp[1], Blp[1]); }
            else          { GEMM_DEPOSIT(Ahp[0], Alp[0], Bhp[0], Blp[0]); }
            __syncthreads();
        }
    }

#pragma unroll
    for (int i = 0; i < 4; i++) {
        int gm0 = blockIdx.y * BM + warpM + i*16 + grp;
#pragma unroll
        for (int j = 0; j < 4; j++) {
            int gn = blockIdx.x * BN + warpN + j*8 + 2*tig;
#pragma unroll
            for (int half = 0; half < 2; half++) {
                int gm = gm0 + half*8;
                if (gm >= M) continue;
#pragma unroll
                for (int q = 0; q < 2; q++) {
                    int n = gn + q;
                    if (n >= N) continue;
                    atomicAdd(&C[(long)gm * ldc + n], acc[i][j][half*2 + q]);
                }
            }
        }
    }
}

// ---------------- causal depthwise conv (K=4) + SiLU ----------------
__global__ void conv_silu_k(const float* __restrict__ xz, const float* __restrict__ cw,
                            const float* __restrict__ cb, float* __restrict__ xb) {
    long idx = (long)blockIdx.x * 256 + threadIdx.x;
    int d = idx & (DI_ - 1);
    long bl = idx >> 11;
    int l = (int)(bl & (L_ - 1));
    float acc = cb[d];
#pragma unroll
    for (int k = 0; k < K_; k++) {
        int lp = l + k - (K_ - 1);
        if (lp >= 0)
            acc = fmaf(cw[d*K_ + k], xz[(bl + (k - (K_-1))) * (2*DI_) + d], acc);
    }
    acc = acc / (1.f + expf(-acc));
    xb[idx] = acc;
}

// ---------------- selective SSM scan + D skip + z-gating ----------------
__global__ void ssm_scan_k(const float* __restrict__ xb, const float* __restrict__ xp,
                           const float* __restrict__ dl, const float* __restrict__ xz,
                           const float* __restrict__ Alog, const float* __restrict__ Dp,
                           float* __restrict__ y) {
    int t = threadIdx.x;
    int g = t >> 4, lane = t & 15;
    int ch = blockIdx.x * 16 + g;
    int b = ch >> 11;
    int d = ch & (DI_ - 1);
    float A = -expf(Alog[d*N_ + lane]);
    float Dv = Dp[d];
    float h = 0.f;
    long rowbase = (long)b * L_;
    for (int l = 0; l < L_; l++) {
        long r = rowbase + l;
        float dv = dl[r*DI_ + d];
        float xv = xb[r*DI_ + d];
        float Bv = xp[r*XPW_ + DTR_ + lane];
        float Cv = xp[r*XPW_ + DTR_ + N_ + lane];
        h = fmaf(expf(dv * A), h, dv * Bv * xv);
        float c = h * Cv;
        c += __shfl_xor_sync(~0u, c, 8);
        c += __shfl_xor_sync(~0u, c, 4);
        c += __shfl_xor_sync(~0u, c, 2);
        c += __shfl_xor_sync(~0u, c, 1);
        if (lane == 0) {
            float z = xz[r*(2*DI_) + DI_ + d];
            float yv = c + xv * Dv;
            y[r*DI_ + d] = yv * (z / (1.f + expf(-z)));
        }
    }
}

// ---------------- head ----------------
__global__ void head_k(const float* __restrict__ fin, const float* __restrict__ hw,
                       float* __restrict__ out) {
    int wid = blockIdx.x * 8 + (threadIdx.x >> 5);
    int lane = threadIdx.x & 31;
    if (wid >= B_ * P_) return;
    int b = wid / P_, p = wid % P_;
    const float* a = fin + (long)b * DM_;
    const float* w = hw + (long)p * DM_;
    float s = 0.f;
    for (int k = lane; k < DM_; k += 32) s = fmaf(a[k], w[k], s);
#pragma unroll
    for (int o = 16; o; o >>= 1) s += __shfl_xor_sync(~0u, s, o);
    if (lane == 0) out[wid] = s;
}

// ---------------- launch ----------------
extern "C" void kernel_launch(void* const* d_in, const int* in_sizes, int n_in,
                              void* d_out, int out_size) {
    const int*   tokens    = (const int*)  d_in[0];
    const float* tok_emb   = (const float*)d_in[1];
    const float* pos_emb   = (const float*)d_in[2];
    const float* ln_w      = (const float*)d_in[3];
    const float* ln_b      = (const float*)d_in[4];
    const float* in_proj_w = (const float*)d_in[5];
    const float* conv_w    = (const float*)d_in[6];
    const float* conv_b    = (const float*)d_in[7];
    const float* xproj_w   = (const float*)d_in[8];
    const float* dt_w      = (const float*)d_in[9];
    const float* dt_b      = (const float*)d_in[10];
    const float* A_log     = (const float*)d_in[11];
    const float* D_param   = (const float*)d_in[12];
    const float* out_proj_w= (const float*)d_in[13];
    const float* fnorm_w   = (const float*)d_in[14];
    const float* fnorm_b   = (const float*)d_in[15];
    const float* head_w    = (const float*)d_in[16];
    float* out = (float*)d_out;

    void *ph, *px, *pxz, *pxb, *pxp, *pdl, *py, *pfin;
    cudaGetSymbolAddress(&ph,  g_h);
    cudaGetSymbolAddress(&px,  g_x);
    cudaGetSymbolAddress(&pxz, g_xz);
    cudaGetSymbolAddress(&pxb, g_xb);
    cudaGetSymbolAddress(&pxp, g_xp);
    cudaGetSymbolAddress(&pdl, g_dl);
    cudaGetSymbolAddress(&py,  g_y);
    cudaGetSymbolAddress(&pfin,g_fin);
    float* h  = (float*)ph;   float* x  = (float*)px;
    float* xz = (float*)pxz;  float* xb = (float*)pxb;
    float* xp = (float*)pxp;  float* dl = (float*)pdl;
    float* y  = (float*)py;   float* fin= (float*)pfin;

    embed_k<<<M_TOK, 256>>>(tokens, tok_emb, pos_emb, h);

    for (int i = 0; i < NL_; i++) {
        ln_k<<<M_TOK, 256>>>(h, DM_, x, DM_, ln_w + i*DM_, ln_b + i*DM_);
        // in_proj: 2048 x 4096 x 1024 (512 CTAs, no split)
        gemm_bf16c<<<dim3(32, 16), 256>>>(M_TOK, 2*DI_, DM_,
            x, DM_, in_proj_w + (long)i*2*DI_*DM_, DM_,
            xz, 2*DI_, nullptr, nullptr, 0, 0);
        conv_silu_k<<<(M_TOK*DI_)/256, 256>>>(xz, conv_w + (long)i*DI_*K_, conv_b + (long)i*DI_, xb);
        // xproj: 2048 x 160 x 2048 — split-K 8, atomic accumulate into zeroed xp
        zero_k<<<(M_TOK*XPW_/4 + 255)/256, 256>>>(xp, M_TOK*XPW_/4);
        gemm_bf16c_sk<<<dim3(2, 16, 8), 256>>>(M_TOK, XPW_, DI_/8,
            xb, DI_, xproj_w + (long)i*XPW_*DI_, DI_,
            xp, XPW_);
        // delta = softplus(dt_r @ dtw.T + dtb): 2048 x 2048 x 128
        gemm_bf16c<<<dim3(16, 16), 256>>>(M_TOK, DI_, DTR_,
            xp, XPW_, dt_w + (long)i*DI_*DTR_, DTR_,
            dl, DI_, dt_b + (long)i*DI_, nullptr, 0, 1);
        ssm_scan_k<<<(B_*DI_)/16, 256>>>(xb, xp, dl, xz,
            A_log + (long)i*DI_*N_, D_param + (long)i*DI_, y);
        // out_proj + residual: 2048 x 1024 x 2048 — split-K 2, h already holds residual
        gemm_bf16c_sk<<<dim3(8, 16, 2), 256>>>(M_TOK, DM_, DI_/2,
            y, DI_, out_proj_w + (long)i*DM_*DI_, DI_,
            h, DM_);
    }

    ln_k<<<B_, 256>>>(h + (long)(L_-1)*DM_, (long)L_*DM_, fin, DM_, fnorm_w, fnorm_b);
    head_k<<<P_, 256>>>(fin, head_w, out);
}